// round 2
// baseline (speedup 1.0000x reference)
#include <cuda_runtime.h>
#include <math.h>

#define B_ 256
#define T_ 512
#define N_ 512
#define H_ 256

// ---------------- scratch (device globals; allocation-free) ----------------
__device__ float g_E[(size_t)B_ * N_ * H_];     // enc_proj [b][n][k]
__device__ float g_Q[(size_t)T_ * B_ * H_];     // q        [t][b][k]
__device__ float g_Hall[(size_t)T_ * B_ * H_];  // hiddens  [t][b][h]
__device__ float g_hid[2][B_ * H_];             // double-buffered hid state
__device__ unsigned g_barcnt[16];               // per-group monotonic barriers

__device__ __forceinline__ float tanha(float x) {
    float y; asm("tanh.approx.f32 %0, %1;" : "=f"(y) : "f"(x)); return y;
}
__device__ __forceinline__ float sigm(float x) { return 1.f / (1.f + expf(-x)); }

__global__ void zero_bar() { if (threadIdx.x < 16) g_barcnt[threadIdx.x] = 0u; }

// ---------------------------------------------------------------------------
// GEMM: Out[m][k] = sum_h X[m][h] * W[k][h]; M=131072, K=256, H=256
// 128x128 tile, 256 threads, 8x8 microtile
// ---------------------------------------------------------------------------
__global__ __launch_bounds__(256) void gemm_kernel(
    const float* __restrict__ X, const float* __restrict__ W,
    float* __restrict__ Out) {
    __shared__ float Xs[16][132];
    __shared__ float Ws[16][132];
    const int tid = threadIdx.x;
    const size_t m0 = (size_t)blockIdx.x * 128;
    const int k0 = blockIdx.y * 128;
    const int f = tid & 3, r = tid >> 2;     // loader: f=h-quad, r=row 0..63
    const int tm = tid >> 4, tk = tid & 15;  // compute: 8x8 tile coords

    const float* Xp = X + (m0 + r) * H_ + f * 4;
    const float* Wp = W + (size_t)(k0 + r) * H_ + f * 4;

    float acc[8][8];
#pragma unroll
    for (int i = 0; i < 8; i++)
#pragma unroll
        for (int j = 0; j < 8; j++) acc[i][j] = 0.f;

    for (int h0 = 0; h0 < H_; h0 += 16) {
        float4 x0 = *(const float4*)(Xp + h0);
        float4 x1 = *(const float4*)(Xp + h0 + (size_t)64 * H_);
        float4 w0 = *(const float4*)(Wp + h0);
        float4 w1 = *(const float4*)(Wp + h0 + (size_t)64 * H_);
        __syncthreads();
        Xs[f * 4 + 0][r] = x0.x; Xs[f * 4 + 1][r] = x0.y;
        Xs[f * 4 + 2][r] = x0.z; Xs[f * 4 + 3][r] = x0.w;
        Xs[f * 4 + 0][r + 64] = x1.x; Xs[f * 4 + 1][r + 64] = x1.y;
        Xs[f * 4 + 2][r + 64] = x1.z; Xs[f * 4 + 3][r + 64] = x1.w;
        Ws[f * 4 + 0][r] = w0.x; Ws[f * 4 + 1][r] = w0.y;
        Ws[f * 4 + 2][r] = w0.z; Ws[f * 4 + 3][r] = w0.w;
        Ws[f * 4 + 0][r + 64] = w1.x; Ws[f * 4 + 1][r + 64] = w1.y;
        Ws[f * 4 + 2][r + 64] = w1.z; Ws[f * 4 + 3][r + 64] = w1.w;
        __syncthreads();
#pragma unroll
        for (int hh = 0; hh < 16; hh++) {
            float xr[8], wr[8];
            *(float4*)&xr[0] = *(const float4*)&Xs[hh][tm * 8];
            *(float4*)&xr[4] = *(const float4*)&Xs[hh][tm * 8 + 4];
            *(float4*)&wr[0] = *(const float4*)&Ws[hh][tk * 8];
            *(float4*)&wr[4] = *(const float4*)&Ws[hh][tk * 8 + 4];
#pragma unroll
            for (int i = 0; i < 8; i++)
#pragma unroll
                for (int j = 0; j < 8; j++)
                    acc[i][j] = fmaf(xr[i], wr[j], acc[i][j]);
        }
    }
#pragma unroll
    for (int i = 0; i < 8; i++) {
        float* op = Out + (m0 + tm * 8 + i) * H_ + k0 + tk * 8;
        *(float4*)op = make_float4(acc[i][0], acc[i][1], acc[i][2], acc[i][3]);
        *(float4*)(op + 4) = make_float4(acc[i][4], acc[i][5], acc[i][6], acc[i][7]);
    }
}

// ---------------------------------------------------------------------------
// LSTM scan: 16 groups x 8 CTAs. CTA j of a group owns h-cols [32j,32j+32)
// and holds the 128 weight rows {i,f,g,o} x 32 cols in smem for the whole scan.
// Cell state lives in registers. One global group-barrier per step.
// ---------------------------------------------------------------------------
#define WSS 260
#define SCAN_SMEM ((128 * WSS + 16 * 256 + 128 * 16 + 128) * 4)

#define DOT4(A, wv, hv)            \
    A = fmaf((wv).x, (hv).x, A);   \
    A = fmaf((wv).y, (hv).y, A);   \
    A = fmaf((wv).z, (hv).z, A);   \
    A = fmaf((wv).w, (hv).w, A)

__global__ __launch_bounds__(256) void scan_kernel(
    const float* __restrict__ W_ih, const float* __restrict__ W_hh,
    const float* __restrict__ b_ih, const float* __restrict__ b_hh) {
    extern __shared__ float sm[];
    float* Ws = sm;                   // [128][WSS]
    float* hid_s = Ws + 128 * WSS;    // [16][256]
    float* red = hid_s + 16 * 256;    // [128][16]
    float* bcs = red + 128 * 16;      // [128]

    const int tid = threadIdx.x;
    const int grp = blockIdx.x >> 3, j = blockIdx.x & 7;
    const int r0 = grp * 16, hbase = j * 32;

    for (int idx = tid; idx < 128 * 256; idx += 256) {
        int q = idx >> 8, h = idx & 255;
        int row = (q >> 5) * 256 + hbase + (q & 31);   // gate-type*256 + hcol
        size_t w = (size_t)row * H_ + h;
        Ws[q * WSS + h] = W_ih[w] + W_hh[w];
    }
    if (tid < 128) {
        int row = (tid >> 5) * 256 + hbase + (tid & 31);
        bcs[tid] = b_ih[row] + b_hh[row];
    }
    for (int idx = tid; idx < 16 * 256; idx += 256) hid_s[idx] = 0.f;
    __syncthreads();

    const int w = tid >> 5, lane = tid & 31;
    const int half = w >> 2, wq = w & 3, hh0 = half * 128;
    float cell[4] = {0.f, 0.f, 0.f, 0.f};

    const float* wp0 = &Ws[(0 * 32 + lane) * WSS + hh0];
    const float* wp1 = &Ws[(1 * 32 + lane) * WSS + hh0];
    const float* wp2 = &Ws[(2 * 32 + lane) * WSS + hh0];
    const float* wp3 = &Ws[(3 * 32 + lane) * WSS + hh0];
    const float* hp = &hid_s[(wq * 4) * 256 + hh0];

    for (int t = 0; t < T_; t++) {
        float acc[4][4];
#pragma unroll
        for (int a = 0; a < 4; a++)
#pragma unroll
            for (int b = 0; b < 4; b++) acc[a][b] = 0.f;

#pragma unroll 4
        for (int c = 0; c < 128; c += 4) {
            float4 w0 = *(const float4*)(wp0 + c);
            float4 w1 = *(const float4*)(wp1 + c);
            float4 w2 = *(const float4*)(wp2 + c);
            float4 w3 = *(const float4*)(wp3 + c);
            float4 h0 = *(const float4*)(hp + c);
            float4 h1 = *(const float4*)(hp + 256 + c);
            float4 h2 = *(const float4*)(hp + 512 + c);
            float4 h3 = *(const float4*)(hp + 768 + c);
            DOT4(acc[0][0], w0, h0); DOT4(acc[0][1], w0, h1);
            DOT4(acc[0][2], w0, h2); DOT4(acc[0][3], w0, h3);
            DOT4(acc[1][0], w1, h0); DOT4(acc[1][1], w1, h1);
            DOT4(acc[1][2], w1, h2); DOT4(acc[1][3], w1, h3);
            DOT4(acc[2][0], w2, h0); DOT4(acc[2][1], w2, h1);
            DOT4(acc[2][2], w2, h2); DOT4(acc[2][3], w2, h3);
            DOT4(acc[3][0], w3, h0); DOT4(acc[3][1], w3, h1);
            DOT4(acc[3][2], w3, h2); DOT4(acc[3][3], w3, h3);
        }

        if (half) {
#pragma unroll
            for (int ty = 0; ty < 4; ty++)
#pragma unroll
                for (int r = 0; r < 4; r++)
                    red[(wq * 32 + lane) * 16 + ty * 4 + r] = acc[ty][r];
        }
        __syncthreads();

        const int buf = (t + 1) & 1;
        if (!half) {
            const float* rp = &red[(wq * 32 + lane) * 16];
#pragma unroll
            for (int r = 0; r < 4; r++) {
                float ig = acc[0][r] + rp[0 + r] + bcs[lane];
                float fg = acc[1][r] + rp[4 + r] + bcs[32 + lane];
                float gg = acc[2][r] + rp[8 + r] + bcs[64 + lane];
                float og = acc[3][r] + rp[12 + r] + bcs[96 + lane];
                cell[r] = sigm(fg) * cell[r] + sigm(ig) * tanhf(gg);
                float hd = sigm(og) * tanhf(cell[r]);
                int row = r0 + wq * 4 + r, col = hbase + lane;
                g_hid[buf][(row << 8) + col] = hd;
                g_Hall[((size_t)t * B_ + row) * H_ + col] = hd;
            }
        }

        // ---- group barrier (8 CTAs) ----
        __syncthreads();
        if (tid == 0) {
            __threadfence();
            atomicAdd(&g_barcnt[grp], 1u);
            unsigned tgt = (unsigned)(t + 1) * 8u;
            while (*((volatile unsigned*)&g_barcnt[grp]) < tgt) {}
            __threadfence();
        }
        __syncthreads();

        // ---- reload full hid slice for this group's 16 batch rows ----
        const float4* src = (const float4*)&g_hid[buf][r0 * H_];
        for (int i2 = tid; i2 < 1024; i2 += 256)
            *(float4*)&hid_s[i2 * 4] = __ldcg(src + i2);
        __syncthreads();
    }
}

// ---------------------------------------------------------------------------
// Attention: out[b][t][n] = sum_h v[h] * tanh(E[b][n][h] + Q[t][b][h])
// 64x64 (t,n) tile per block, MUFU tanh.approx, padded smem stride 260
// ---------------------------------------------------------------------------
#define AST 260
#define ATTN_SMEM ((64 * AST * 2 + 256) * 4)

#define AT1(A, vc, qc, ec) A = fmaf(vc, tanha((qc) + (ec)), A)
#define AT4(A, qv, ev)                 \
    AT1(A, vv.x, (qv).x, (ev).x);      \
    AT1(A, vv.y, (qv).y, (ev).y);      \
    AT1(A, vv.z, (qv).z, (ev).z);      \
    AT1(A, vv.w, (qv).w, (ev).w)

__global__ __launch_bounds__(256) void attn_kernel(
    const float* __restrict__ v, float* __restrict__ out) {
    extern __shared__ float sm[];
    float* Qs = sm;              // [64][AST]
    float* Es = Qs + 64 * AST;   // [64][AST]
    float* vs = Es + 64 * AST;   // [256]

    const int tid = threadIdx.x;
    const int b = blockIdx.z, t0 = blockIdx.y << 6, n0 = blockIdx.x << 6;

    if (tid < 64) ((float4*)vs)[tid] = ((const float4*)v)[tid];
    for (int i = tid; i < 4096; i += 256) {
        int row = i >> 6, c4 = i & 63;
        float4 q = __ldg((const float4*)(g_Q + ((size_t)(t0 + row) * B_ + b) * H_) + c4);
        *(float4*)&Qs[row * AST + c4 * 4] = q;
        float4 e = __ldg((const float4*)(g_E + ((size_t)b * N_ + n0 + row) * H_) + c4);
        *(float4*)&Es[row * AST + c4 * 4] = e;
    }
    __syncthreads();

    const int tx = tid & 15, ty = tid >> 4;   // thread covers t = t0+ty+16i, n = n0+tx+16j
    float acc[4][4];
#pragma unroll
    for (int i = 0; i < 4; i++)
#pragma unroll
        for (int jj = 0; jj < 4; jj++) acc[i][jj] = 0.f;

    const float* qp = &Qs[ty * AST];
    const float* ep = &Es[tx * AST];
#pragma unroll 2
    for (int h = 0; h < 256; h += 4) {
        float4 vv = *(const float4*)&vs[h];
        float4 q0 = *(const float4*)(qp + h);
        float4 q1 = *(const float4*)(qp + 16 * AST + h);
        float4 q2 = *(const float4*)(qp + 32 * AST + h);
        float4 q3 = *(const float4*)(qp + 48 * AST + h);
        float4 e0 = *(const float4*)(ep + h);
        float4 e1 = *(const float4*)(ep + 16 * AST + h);
        float4 e2 = *(const float4*)(ep + 32 * AST + h);
        float4 e3 = *(const float4*)(ep + 48 * AST + h);
        AT4(acc[0][0], q0, e0); AT4(acc[0][1], q0, e1);
        AT4(acc[0][2], q0, e2); AT4(acc[0][3], q0, e3);
        AT4(acc[1][0], q1, e0); AT4(acc[1][1], q1, e1);
        AT4(acc[1][2], q1, e2); AT4(acc[1][3], q1, e3);
        AT4(acc[2][0], q2, e0); AT4(acc[2][1], q2, e1);
        AT4(acc[2][2], q2, e2); AT4(acc[2][3], q2, e3);
        AT4(acc[3][0], q3, e0); AT4(acc[3][1], q3, e1);
        AT4(acc[3][2], q3, e2); AT4(acc[3][3], q3, e3);
    }

#pragma unroll
    for (int i = 0; i < 4; i++) {
        float* op = out + ((size_t)b * T_ + t0 + ty + 16 * i) * N_ + n0 + tx;
#pragma unroll
        for (int jj = 0; jj < 4; jj++) op[16 * jj] = acc[i][jj];
    }
}

// ---------------------------------------------------------------------------
extern "C" void kernel_launch(void* const* d_in, const int* in_sizes, int n_in,
                              void* d_out, int out_size) {
    const float* enc   = (const float*)d_in[0];
    const float* W_ih  = (const float*)d_in[1];
    const float* W_hh  = (const float*)d_in[2];
    const float* b_ih  = (const float*)d_in[3];
    const float* b_hh  = (const float*)d_in[4];
    const float* W_ref = (const float*)d_in[5];
    const float* W_q   = (const float*)d_in[6];
    const float* v     = (const float*)d_in[7];
    float* out = (float*)d_out;

    cudaFuncSetAttribute(scan_kernel, cudaFuncAttributeMaxDynamicSharedMemorySize, SCAN_SMEM);
    cudaFuncSetAttribute(attn_kernel, cudaFuncAttributeMaxDynamicSharedMemorySize, ATTN_SMEM);

    void *pE, *pQ, *pH;
    cudaGetSymbolAddress(&pE, g_E);
    cudaGetSymbolAddress(&pQ, g_Q);
    cudaGetSymbolAddress(&pH, g_Hall);

    zero_bar<<<1, 32>>>();
    gemm_kernel<<<dim3(1024, 2), 256>>>(enc, W_ref, (float*)pE);
    scan_kernel<<<128, 256, SCAN_SMEM>>>(W_ih, W_hh, b_ih, b_hh);
    gemm_kernel<<<dim3(1024, 2), 256>>>((const float*)pH, W_q, (float*)pQ);
    attn_kernel<<<dim3(8, 8, 256), 256, ATTN_SMEM>>>(v, out);
}

// round 3
// speedup vs baseline: 1.0280x; 1.0280x over previous
#include <cuda_runtime.h>
#include <cuda_fp16.h>
#include <math.h>

#define B_ 256
#define T_ 512
#define N_ 512
#define H_ 256

typedef unsigned long long u64;

// ---------------- scratch (device globals; allocation-free) ----------------
__device__ float g_E[(size_t)B_ * N_ * H_];     // enc_proj [b][n][k]
__device__ float g_Q[(size_t)T_ * B_ * H_];     // q        [t][b][k]
__device__ float g_Hall[(size_t)T_ * B_ * H_];  // hiddens  [t][b][h]
__device__ float g_hid[2][B_ * H_];             // double-buffered hid state
__device__ unsigned g_barcnt[16];               // per-group monotonic barriers

// ---------------- fast-math helpers ----------------
__device__ __forceinline__ float tanha(float x) {
    float y; asm("tanh.approx.f32 %0, %1;" : "=f"(y) : "f"(x)); return y;
}
__device__ __forceinline__ float sigma_(float x) {          // sigmoid via MUFU tanh
    return fmaf(0.5f, tanha(0.5f * x), 0.5f);
}
// packed fp32x2 fma (Blackwell FFMA2)
__device__ __forceinline__ u64 ffma2(u64 a, u64 b, u64 c) {
    u64 r; asm("fma.rn.f32x2 %0, %1, %2, %3;" : "=l"(r) : "l"(a), "l"(b), "l"(c));
    return r;
}
__device__ __forceinline__ u64 fdup2(float x) {
    u64 r; asm("mov.b64 %0, {%1, %1};" : "=l"(r) : "f"(x)); return r;
}
__device__ __forceinline__ float fsum2(u64 a) {
    float lo, hi; asm("mov.b64 {%0, %1}, %2;" : "=f"(lo), "=f"(hi) : "l"(a));
    return lo + hi;
}
__device__ __forceinline__ float2 funpk(u64 a) {
    float2 f; asm("mov.b64 {%0, %1}, %2;" : "=f"(f.x), "=f"(f.y) : "l"(a));
    return f;
}
// two tanh per MUFU op via f16x2; fp32 in/out
__device__ __forceinline__ float2 tanh2(float x0, float x1) {
    __half2 h = __floats2half2_rn(x0, x1);
    unsigned hp = *reinterpret_cast<unsigned*>(&h);
    unsigned tp;
    asm("tanh.approx.f16x2 %0, %1;" : "=r"(tp) : "r"(hp));
    __half2 th = *reinterpret_cast<__half2*>(&tp);
    return __half22float2(th);
}

__global__ void zero_bar() { if (threadIdx.x < 16) g_barcnt[threadIdx.x] = 0u; }

// ---------------------------------------------------------------------------
// GEMM: Out[m][k] = sum_h X[m][h] * W[k][h]; M=131072, K=256, H=256
// 128x128 tile, 256 threads, 8x8 microtile, packed f32x2 FMA
// ---------------------------------------------------------------------------
__global__ __launch_bounds__(256) void gemm_kernel(
    const float* __restrict__ X, const float* __restrict__ W,
    float* __restrict__ Out) {
    __shared__ __align__(16) float Xs[16][132];
    __shared__ __align__(16) float Ws[16][132];
    const int tid = threadIdx.x;
    const size_t m0 = (size_t)blockIdx.x * 128;
    const int k0 = blockIdx.y * 128;
    const int f = tid & 3, r = tid >> 2;
    const int tm = tid >> 4, tk = tid & 15;

    const float* Xp = X + (m0 + r) * H_ + f * 4;
    const float* Wp = W + (size_t)(k0 + r) * H_ + f * 4;

    u64 acc[8][4];
#pragma unroll
    for (int i = 0; i < 8; i++)
#pragma unroll
        for (int j = 0; j < 4; j++) acc[i][j] = 0ULL;

    for (int h0 = 0; h0 < H_; h0 += 16) {
        float4 x0 = *(const float4*)(Xp + h0);
        float4 x1 = *(const float4*)(Xp + h0 + (size_t)64 * H_);
        float4 w0 = *(const float4*)(Wp + h0);
        float4 w1 = *(const float4*)(Wp + h0 + (size_t)64 * H_);
        __syncthreads();
        Xs[f * 4 + 0][r] = x0.x; Xs[f * 4 + 1][r] = x0.y;
        Xs[f * 4 + 2][r] = x0.z; Xs[f * 4 + 3][r] = x0.w;
        Xs[f * 4 + 0][r + 64] = x1.x; Xs[f * 4 + 1][r + 64] = x1.y;
        Xs[f * 4 + 2][r + 64] = x1.z; Xs[f * 4 + 3][r + 64] = x1.w;
        Ws[f * 4 + 0][r] = w0.x; Ws[f * 4 + 1][r] = w0.y;
        Ws[f * 4 + 2][r] = w0.z; Ws[f * 4 + 3][r] = w0.w;
        Ws[f * 4 + 0][r + 64] = w1.x; Ws[f * 4 + 1][r + 64] = w1.y;
        Ws[f * 4 + 2][r + 64] = w1.z; Ws[f * 4 + 3][r + 64] = w1.w;
        __syncthreads();
#pragma unroll
        for (int hh = 0; hh < 16; hh++) {
            float xr[8];
            *(float4*)&xr[0] = *(const float4*)&Xs[hh][tm * 8];
            *(float4*)&xr[4] = *(const float4*)&Xs[hh][tm * 8 + 4];
            ulonglong2 wa = *(const ulonglong2*)&Ws[hh][tk * 8];
            ulonglong2 wb = *(const ulonglong2*)&Ws[hh][tk * 8 + 4];
#pragma unroll
            for (int i = 0; i < 8; i++) {
                u64 xd = fdup2(xr[i]);
                acc[i][0] = ffma2(xd, wa.x, acc[i][0]);
                acc[i][1] = ffma2(xd, wa.y, acc[i][1]);
                acc[i][2] = ffma2(xd, wb.x, acc[i][2]);
                acc[i][3] = ffma2(xd, wb.y, acc[i][3]);
            }
        }
    }
#pragma unroll
    for (int i = 0; i < 8; i++) {
        float2 p0 = funpk(acc[i][0]), p1 = funpk(acc[i][1]);
        float2 p2 = funpk(acc[i][2]), p3 = funpk(acc[i][3]);
        float* op = Out + (m0 + tm * 8 + i) * H_ + k0 + tk * 8;
        *(float4*)op = make_float4(p0.x, p0.y, p1.x, p1.y);
        *(float4*)(op + 4) = make_float4(p2.x, p2.y, p3.x, p3.y);
    }
}

// ---------------------------------------------------------------------------
// LSTM scan: 16 groups x 8 CTAs. CTA j of a group owns h-cols [32j,32j+32)
// and holds the 128 weight rows {i,f,g,o} x 32 cols in smem for the whole scan.
// Cell state lives in registers. One global group-barrier per step.
// ---------------------------------------------------------------------------
#define WSS 260
#define SCAN_SMEM ((128 * WSS + 16 * 256 + 128 * 16 + 128) * 4)

#define PDOT4(A, wv, hv)                 \
    A = ffma2((wv).x, (hv).x, A);        \
    A = ffma2((wv).y, (hv).y, A)

__global__ __launch_bounds__(256) void scan_kernel(
    const float* __restrict__ W_ih, const float* __restrict__ W_hh,
    const float* __restrict__ b_ih, const float* __restrict__ b_hh) {
    extern __shared__ float sm[];
    float* Ws = sm;                   // [128][WSS]
    float* hid_s = Ws + 128 * WSS;    // [16][256]
    float* red = hid_s + 16 * 256;    // [128][16]
    float* bcs = red + 128 * 16;      // [128]

    const int tid = threadIdx.x;
    const int grp = blockIdx.x >> 3, j = blockIdx.x & 7;
    const int r0 = grp * 16, hbase = j * 32;

    for (int idx = tid; idx < 128 * 256; idx += 256) {
        int q = idx >> 8, h = idx & 255;
        int row = (q >> 5) * 256 + hbase + (q & 31);
        size_t w = (size_t)row * H_ + h;
        Ws[q * WSS + h] = W_ih[w] + W_hh[w];
    }
    if (tid < 128) {
        int row = (tid >> 5) * 256 + hbase + (tid & 31);
        bcs[tid] = b_ih[row] + b_hh[row];
    }
    for (int idx = tid; idx < 16 * 256; idx += 256) hid_s[idx] = 0.f;
    __syncthreads();

    const int w = tid >> 5, lane = tid & 31;
    const int half = w >> 2, wq = w & 3, hh0 = half * 128;
    float cell[4] = {0.f, 0.f, 0.f, 0.f};

    const float* wp0 = &Ws[(0 * 32 + lane) * WSS + hh0];
    const float* wp1 = &Ws[(1 * 32 + lane) * WSS + hh0];
    const float* wp2 = &Ws[(2 * 32 + lane) * WSS + hh0];
    const float* wp3 = &Ws[(3 * 32 + lane) * WSS + hh0];
    const float* hp = &hid_s[(wq * 4) * 256 + hh0];

    for (int t = 0; t < T_; t++) {
        u64 acc[4][4];
#pragma unroll
        for (int a = 0; a < 4; a++)
#pragma unroll
            for (int b = 0; b < 4; b++) acc[a][b] = 0ULL;

#pragma unroll 4
        for (int c = 0; c < 128; c += 4) {
            ulonglong2 w0 = *(const ulonglong2*)(wp0 + c);
            ulonglong2 w1 = *(const ulonglong2*)(wp1 + c);
            ulonglong2 w2 = *(const ulonglong2*)(wp2 + c);
            ulonglong2 w3 = *(const ulonglong2*)(wp3 + c);
            ulonglong2 h0 = *(const ulonglong2*)(hp + c);
            ulonglong2 h1 = *(const ulonglong2*)(hp + 256 + c);
            ulonglong2 h2 = *(const ulonglong2*)(hp + 512 + c);
            ulonglong2 h3 = *(const ulonglong2*)(hp + 768 + c);
            PDOT4(acc[0][0], w0, h0); PDOT4(acc[0][1], w0, h1);
            PDOT4(acc[0][2], w0, h2); PDOT4(acc[0][3], w0, h3);
            PDOT4(acc[1][0], w1, h0); PDOT4(acc[1][1], w1, h1);
            PDOT4(acc[1][2], w1, h2); PDOT4(acc[1][3], w1, h3);
            PDOT4(acc[2][0], w2, h0); PDOT4(acc[2][1], w2, h1);
            PDOT4(acc[2][2], w2, h2); PDOT4(acc[2][3], w2, h3);
            PDOT4(acc[3][0], w3, h0); PDOT4(acc[3][1], w3, h1);
            PDOT4(acc[3][2], w3, h2); PDOT4(acc[3][3], w3, h3);
        }

        if (half) {
#pragma unroll
            for (int ty = 0; ty < 4; ty++)
#pragma unroll
                for (int r = 0; r < 4; r++)
                    red[(wq * 32 + lane) * 16 + ty * 4 + r] = fsum2(acc[ty][r]);
        }
        __syncthreads();

        const int buf = (t + 1) & 1;
        if (!half) {
            const float* rp = &red[(wq * 32 + lane) * 16];
#pragma unroll
            for (int r = 0; r < 4; r++) {
                float ig = fsum2(acc[0][r]) + rp[0 + r] + bcs[lane];
                float fg = fsum2(acc[1][r]) + rp[4 + r] + bcs[32 + lane];
                float gg = fsum2(acc[2][r]) + rp[8 + r] + bcs[64 + lane];
                float og = fsum2(acc[3][r]) + rp[12 + r] + bcs[96 + lane];
                cell[r] = sigma_(fg) * cell[r] + sigma_(ig) * tanha(gg);
                float hd = sigma_(og) * tanha(cell[r]);
                int row = r0 + wq * 4 + r, col = hbase + lane;
                g_hid[buf][(row << 8) + col] = hd;
                g_Hall[((size_t)t * B_ + row) * H_ + col] = hd;
            }
        }

        // ---- group barrier (8 CTAs) ----
        __syncthreads();
        if (tid == 0) {
            __threadfence();
            atomicAdd(&g_barcnt[grp], 1u);
            unsigned tgt = (unsigned)(t + 1) * 8u;
            while (*((volatile unsigned*)&g_barcnt[grp]) < tgt) {}
            __threadfence();
        }
        __syncthreads();

        // ---- reload full hid slice for this group's 16 batch rows ----
        const float4* src = (const float4*)&g_hid[buf][r0 * H_];
        for (int i2 = tid; i2 < 1024; i2 += 256)
            *(float4*)&hid_s[i2 * 4] = __ldcg(src + i2);
        __syncthreads();
    }
}

// ---------------------------------------------------------------------------
// Attention: out[b][t][n] = sum_h v[h] * tanh(E[b][n][h] + Q[t][b][h])
// 64x64 (t,n) tile per block; tanh.approx.f16x2 (2 tanh/MUFU op), fp32 accum
// ---------------------------------------------------------------------------
#define AST 260
#define ATTN_SMEM ((64 * AST * 2 + 256) * 4)

#define AT4(A, qv, ev)                                        \
    {                                                         \
        float2 t01 = tanh2((qv).x + (ev).x, (qv).y + (ev).y); \
        float2 t23 = tanh2((qv).z + (ev).z, (qv).w + (ev).w); \
        A = fmaf(vv.x, t01.x, A);                             \
        A = fmaf(vv.y, t01.y, A);                             \
        A = fmaf(vv.z, t23.x, A);                             \
        A = fmaf(vv.w, t23.y, A);                             \
    }

__global__ __launch_bounds__(256) void attn_kernel(
    const float* __restrict__ v, float* __restrict__ out) {
    extern __shared__ float sm[];
    float* Qs = sm;              // [64][AST]
    float* Es = Qs + 64 * AST;   // [64][AST]
    float* vs = Es + 64 * AST;   // [256]

    const int tid = threadIdx.x;
    const int b = blockIdx.z, t0 = blockIdx.y << 6, n0 = blockIdx.x << 6;

    if (tid < 64) ((float4*)vs)[tid] = ((const float4*)v)[tid];
    for (int i = tid; i < 4096; i += 256) {
        int row = i >> 6, c4 = i & 63;
        float4 q = __ldg((const float4*)(g_Q + ((size_t)(t0 + row) * B_ + b) * H_) + c4);
        *(float4*)&Qs[row * AST + c4 * 4] = q;
        float4 e = __ldg((const float4*)(g_E + ((size_t)b * N_ + n0 + row) * H_) + c4);
        *(float4*)&Es[row * AST + c4 * 4] = e;
    }
    __syncthreads();

    const int tx = tid & 15, ty = tid >> 4;
    float acc[4][4];
#pragma unroll
    for (int i = 0; i < 4; i++)
#pragma unroll
        for (int jj = 0; jj < 4; jj++) acc[i][jj] = 0.f;

    const float* qp = &Qs[ty * AST];
    const float* ep = &Es[tx * AST];
#pragma unroll 2
    for (int h = 0; h < 256; h += 4) {
        float4 vv = *(const float4*)&vs[h];
        float4 q0 = *(const float4*)(qp + h);
        float4 q1 = *(const float4*)(qp + 16 * AST + h);
        float4 q2 = *(const float4*)(qp + 32 * AST + h);
        float4 q3 = *(const float4*)(qp + 48 * AST + h);
        float4 e0 = *(const float4*)(ep + h);
        float4 e1 = *(const float4*)(ep + 16 * AST + h);
        float4 e2 = *(const float4*)(ep + 32 * AST + h);
        float4 e3 = *(const float4*)(ep + 48 * AST + h);
        AT4(acc[0][0], q0, e0); AT4(acc[0][1], q0, e1);
        AT4(acc[0][2], q0, e2); AT4(acc[0][3], q0, e3);
        AT4(acc[1][0], q1, e0); AT4(acc[1][1], q1, e1);
        AT4(acc[1][2], q1, e2); AT4(acc[1][3], q1, e3);
        AT4(acc[2][0], q2, e0); AT4(acc[2][1], q2, e1);
        AT4(acc[2][2], q2, e2); AT4(acc[2][3], q2, e3);
        AT4(acc[3][0], q3, e0); AT4(acc[3][1], q3, e1);
        AT4(acc[3][2], q3, e2); AT4(acc[3][3], q3, e3);
    }

#pragma unroll
    for (int i = 0; i < 4; i++) {
        float* op = out + ((size_t)b * T_ + t0 + ty + 16 * i) * N_ + n0 + tx;
#pragma unroll
        for (int jj = 0; jj < 4; jj++) op[16 * jj] = acc[i][jj];
    }
}

// ---------------------------------------------------------------------------
extern "C" void kernel_launch(void* const* d_in, const int* in_sizes, int n_in,
                              void* d_out, int out_size) {
    const float* enc   = (const float*)d_in[0];
    const float* W_ih  = (const float*)d_in[1];
    const float* W_hh  = (const float*)d_in[2];
    const float* b_ih  = (const float*)d_in[3];
    const float* b_hh  = (const float*)d_in[4];
    const float* W_ref = (const float*)d_in[5];
    const float* W_q   = (const float*)d_in[6];
    const float* v     = (const float*)d_in[7];
    float* out = (float*)d_out;

    cudaFuncSetAttribute(scan_kernel, cudaFuncAttributeMaxDynamicSharedMemorySize, SCAN_SMEM);
    cudaFuncSetAttribute(attn_kernel, cudaFuncAttributeMaxDynamicSharedMemorySize, ATTN_SMEM);

    void *pE, *pQ, *pH;
    cudaGetSymbolAddress(&pE, g_E);
    cudaGetSymbolAddress(&pQ, g_Q);
    cudaGetSymbolAddress(&pH, g_Hall);

    zero_bar<<<1, 32>>>();
    gemm_kernel<<<dim3(1024, 2), 256>>>(enc, W_ref, (float*)pE);
    scan_kernel<<<128, 256, SCAN_SMEM>>>(W_ih, W_hh, b_ih, b_hh);
    gemm_kernel<<<dim3(1024, 2), 256>>>((const float*)pH, W_q, (float*)pQ);
    attn_kernel<<<dim3(8, 8, 256), 256, ATTN_SMEM>>>(v, out);
}

// round 4
// speedup vs baseline: 1.1644x; 1.1327x over previous
#include <cuda_runtime.h>
#include <cuda_fp16.h>
#include <math.h>

#define B_ 256
#define T_ 512
#define N_ 512
#define H_ 256

typedef unsigned long long u64;
typedef unsigned u32;

// ---------------- scratch (device globals; allocation-free) ----------------
__device__ u32   g_Eh[(size_t)B_ * N_ * (H_ / 2)];   // enc_proj half2 [b][n][h2]
__device__ u32   g_Qh[(size_t)T_ * B_ * (H_ / 2)];   // q       half2 [t][b][h2]
__device__ float g_Hall[(size_t)T_ * B_ * H_];       // hiddens f32   [t][b][h]
__device__ float g_hid[2][B_ * H_];                  // double-buffered hid
__device__ unsigned g_barcnt[16];                    // per-group barriers

// ---------------- fast-math helpers ----------------
__device__ __forceinline__ float tanha(float x) {
    float y; asm("tanh.approx.f32 %0, %1;" : "=f"(y) : "f"(x)); return y;
}
__device__ __forceinline__ float sigma_(float x) {
    return fmaf(0.5f, tanha(0.5f * x), 0.5f);
}
__device__ __forceinline__ u64 ffma2(u64 a, u64 b, u64 c) {
    u64 r; asm("fma.rn.f32x2 %0, %1, %2, %3;" : "=l"(r) : "l"(a), "l"(b), "l"(c));
    return r;
}
__device__ __forceinline__ u64 fdup2(float x) {
    u64 r; asm("mov.b64 %0, {%1, %1};" : "=l"(r) : "f"(x)); return r;
}
__device__ __forceinline__ float fsum2(u64 a) {
    float lo, hi; asm("mov.b64 {%0, %1}, %2;" : "=f"(lo), "=f"(hi) : "l"(a));
    return lo + hi;
}
__device__ __forceinline__ float2 funpk(u64 a) {
    float2 f; asm("mov.b64 {%0, %1}, %2;" : "=f"(f.x), "=f"(f.y) : "l"(a));
    return f;
}
__device__ __forceinline__ u32 packh2(float a, float b) {
    __half2 h = __floats2half2_rn(a, b);
    return *reinterpret_cast<u32*>(&h);
}
// half(low 16 bits of hb) -> float, pure ALU (exact for normals; subnormal
// mishandling bounded by 6e-5 abs -- negligible here)
__device__ __forceinline__ float h2f_fast(u32 hb) {
    u32 r = ((hb & 0x8000u) << 16) + ((hb & 0x7FFFu) << 13) + 0x38000000u;
    return __uint_as_float(r);
}

__global__ void zero_bar() { if (threadIdx.x < 16) g_barcnt[threadIdx.x] = 0u; }

// ---------------------------------------------------------------------------
// GEMM: OutH[m][k](half2-packed) = sum_h X[m][h] * W[k][h]; M=131072,K=256,H=256
// ---------------------------------------------------------------------------
__global__ __launch_bounds__(256) void gemm_kernel(
    const float* __restrict__ X, const float* __restrict__ W,
    u32* __restrict__ OutH) {
    __shared__ __align__(16) float Xs[16][132];
    __shared__ __align__(16) float Ws[16][132];
    const int tid = threadIdx.x;
    const size_t m0 = (size_t)blockIdx.x * 128;
    const int k0 = blockIdx.y * 128;
    const int f = tid & 3, r = tid >> 2;
    const int tm = tid >> 4, tk = tid & 15;

    const float* Xp = X + (m0 + r) * H_ + f * 4;
    const float* Wp = W + (size_t)(k0 + r) * H_ + f * 4;

    u64 acc[8][4];
#pragma unroll
    for (int i = 0; i < 8; i++)
#pragma unroll
        for (int j = 0; j < 4; j++) acc[i][j] = 0ULL;

    for (int h0 = 0; h0 < H_; h0 += 16) {
        float4 x0 = *(const float4*)(Xp + h0);
        float4 x1 = *(const float4*)(Xp + h0 + (size_t)64 * H_);
        float4 w0 = *(const float4*)(Wp + h0);
        float4 w1 = *(const float4*)(Wp + h0 + (size_t)64 * H_);
        __syncthreads();
        Xs[f * 4 + 0][r] = x0.x; Xs[f * 4 + 1][r] = x0.y;
        Xs[f * 4 + 2][r] = x0.z; Xs[f * 4 + 3][r] = x0.w;
        Xs[f * 4 + 0][r + 64] = x1.x; Xs[f * 4 + 1][r + 64] = x1.y;
        Xs[f * 4 + 2][r + 64] = x1.z; Xs[f * 4 + 3][r + 64] = x1.w;
        Ws[f * 4 + 0][r] = w0.x; Ws[f * 4 + 1][r] = w0.y;
        Ws[f * 4 + 2][r] = w0.z; Ws[f * 4 + 3][r] = w0.w;
        Ws[f * 4 + 0][r + 64] = w1.x; Ws[f * 4 + 1][r + 64] = w1.y;
        Ws[f * 4 + 2][r + 64] = w1.z; Ws[f * 4 + 3][r + 64] = w1.w;
        __syncthreads();
#pragma unroll
        for (int hh = 0; hh < 16; hh++) {
            float xr[8];
            *(float4*)&xr[0] = *(const float4*)&Xs[hh][tm * 8];
            *(float4*)&xr[4] = *(const float4*)&Xs[hh][tm * 8 + 4];
            ulonglong2 wa = *(const ulonglong2*)&Ws[hh][tk * 8];
            ulonglong2 wb = *(const ulonglong2*)&Ws[hh][tk * 8 + 4];
#pragma unroll
            for (int i = 0; i < 8; i++) {
                u64 xd = fdup2(xr[i]);
                acc[i][0] = ffma2(xd, wa.x, acc[i][0]);
                acc[i][1] = ffma2(xd, wa.y, acc[i][1]);
                acc[i][2] = ffma2(xd, wb.x, acc[i][2]);
                acc[i][3] = ffma2(xd, wb.y, acc[i][3]);
            }
        }
    }
#pragma unroll
    for (int i = 0; i < 8; i++) {
        float2 p0 = funpk(acc[i][0]), p1 = funpk(acc[i][1]);
        float2 p2 = funpk(acc[i][2]), p3 = funpk(acc[i][3]);
        uint4 o;
        o.x = packh2(p0.x, p0.y); o.y = packh2(p1.x, p1.y);
        o.z = packh2(p2.x, p2.y); o.w = packh2(p3.x, p3.y);
        u32* op = OutH + (m0 + tm * 8 + i) * (H_ / 2) + (k0 >> 1) + tk * 4;
        *(uint4*)op = o;
    }
}

// ---------------------------------------------------------------------------
// LSTM scan (unchanged from R3): 16 groups x 8 CTAs; weights resident in smem
// ---------------------------------------------------------------------------
#define WSS 260
#define SCAN_SMEM ((128 * WSS + 16 * 256 + 128 * 16 + 128) * 4)

#define PDOT4(A, wv, hv)                 \
    A = ffma2((wv).x, (hv).x, A);        \
    A = ffma2((wv).y, (hv).y, A)

__global__ __launch_bounds__(256) void scan_kernel(
    const float* __restrict__ W_ih, const float* __restrict__ W_hh,
    const float* __restrict__ b_ih, const float* __restrict__ b_hh) {
    extern __shared__ float sm[];
    float* Ws = sm;
    float* hid_s = Ws + 128 * WSS;
    float* red = hid_s + 16 * 256;
    float* bcs = red + 128 * 16;

    const int tid = threadIdx.x;
    const int grp = blockIdx.x >> 3, j = blockIdx.x & 7;
    const int r0 = grp * 16, hbase = j * 32;

    for (int idx = tid; idx < 128 * 256; idx += 256) {
        int q = idx >> 8, h = idx & 255;
        int row = (q >> 5) * 256 + hbase + (q & 31);
        size_t w = (size_t)row * H_ + h;
        Ws[q * WSS + h] = W_ih[w] + W_hh[w];
    }
    if (tid < 128) {
        int row = (tid >> 5) * 256 + hbase + (tid & 31);
        bcs[tid] = b_ih[row] + b_hh[row];
    }
    for (int idx = tid; idx < 16 * 256; idx += 256) hid_s[idx] = 0.f;
    __syncthreads();

    const int w = tid >> 5, lane = tid & 31;
    const int half = w >> 2, wq = w & 3, hh0 = half * 128;
    float cell[4] = {0.f, 0.f, 0.f, 0.f};

    const float* wp0 = &Ws[(0 * 32 + lane) * WSS + hh0];
    const float* wp1 = &Ws[(1 * 32 + lane) * WSS + hh0];
    const float* wp2 = &Ws[(2 * 32 + lane) * WSS + hh0];
    const float* wp3 = &Ws[(3 * 32 + lane) * WSS + hh0];
    const float* hp = &hid_s[(wq * 4) * 256 + hh0];

    for (int t = 0; t < T_; t++) {
        u64 acc[4][4];
#pragma unroll
        for (int a = 0; a < 4; a++)
#pragma unroll
            for (int b = 0; b < 4; b++) acc[a][b] = 0ULL;

#pragma unroll 4
        for (int c = 0; c < 128; c += 4) {
            ulonglong2 w0 = *(const ulonglong2*)(wp0 + c);
            ulonglong2 w1 = *(const ulonglong2*)(wp1 + c);
            ulonglong2 w2 = *(const ulonglong2*)(wp2 + c);
            ulonglong2 w3 = *(const ulonglong2*)(wp3 + c);
            ulonglong2 h0 = *(const ulonglong2*)(hp + c);
            ulonglong2 h1 = *(const ulonglong2*)(hp + 256 + c);
            ulonglong2 h2 = *(const ulonglong2*)(hp + 512 + c);
            ulonglong2 h3 = *(const ulonglong2*)(hp + 768 + c);
            PDOT4(acc[0][0], w0, h0); PDOT4(acc[0][1], w0, h1);
            PDOT4(acc[0][2], w0, h2); PDOT4(acc[0][3], w0, h3);
            PDOT4(acc[1][0], w1, h0); PDOT4(acc[1][1], w1, h1);
            PDOT4(acc[1][2], w1, h2); PDOT4(acc[1][3], w1, h3);
            PDOT4(acc[2][0], w2, h0); PDOT4(acc[2][1], w2, h1);
            PDOT4(acc[2][2], w2, h2); PDOT4(acc[2][3], w2, h3);
            PDOT4(acc[3][0], w3, h0); PDOT4(acc[3][1], w3, h1);
            PDOT4(acc[3][2], w3, h2); PDOT4(acc[3][3], w3, h3);
        }

        if (half) {
#pragma unroll
            for (int ty = 0; ty < 4; ty++)
#pragma unroll
                for (int r = 0; r < 4; r++)
                    red[(wq * 32 + lane) * 16 + ty * 4 + r] = fsum2(acc[ty][r]);
        }
        __syncthreads();

        const int buf = (t + 1) & 1;
        if (!half) {
            const float* rp = &red[(wq * 32 + lane) * 16];
#pragma unroll
            for (int r = 0; r < 4; r++) {
                float ig = fsum2(acc[0][r]) + rp[0 + r] + bcs[lane];
                float fg = fsum2(acc[1][r]) + rp[4 + r] + bcs[32 + lane];
                float gg = fsum2(acc[2][r]) + rp[8 + r] + bcs[64 + lane];
                float og = fsum2(acc[3][r]) + rp[12 + r] + bcs[96 + lane];
                cell[r] = sigma_(fg) * cell[r] + sigma_(ig) * tanha(gg);
                float hd = sigma_(og) * tanha(cell[r]);
                int row = r0 + wq * 4 + r, col = hbase + lane;
                g_hid[buf][(row << 8) + col] = hd;
                g_Hall[((size_t)t * B_ + row) * H_ + col] = hd;
            }
        }

        __syncthreads();
        if (tid == 0) {
            __threadfence();
            atomicAdd(&g_barcnt[grp], 1u);
            unsigned tgt = (unsigned)(t + 1) * 8u;
            while (*((volatile unsigned*)&g_barcnt[grp]) < tgt) {}
            __threadfence();
        }
        __syncthreads();

        const float4* src = (const float4*)&g_hid[buf][r0 * H_];
        for (int i2 = tid; i2 < 1024; i2 += 256)
            *(float4*)&hid_s[i2 * 4] = __ldcg(src + i2);
        __syncthreads();
    }
}

// ---------------------------------------------------------------------------
// Attention: out[b][t][n] = sum_h v[h]*tanh(E[b][n][h]+Q[t][b][h])
// All-half pipeline: HADD2 -> tanh.f16x2 -> HFMA2 (chunked) -> ALU widen
// 64x64 (t,n) tile per block; E/Q tiles as half2 in smem
// ---------------------------------------------------------------------------
#define ASU 132
#define ATTN_SMEM ((2 * 64 * ASU + 128) * 4)

#define HADD2A(r, a, b) asm("add.rn.f16x2 %0, %1, %2;" : "=r"(r) : "r"(a), "r"(b))
#define TANH2A(r, a)    asm("tanh.approx.f16x2 %0, %1;" : "=r"(r) : "r"(a))
#define HFMA2A(d, a, b) asm("fma.rn.f16x2 %0, %1, %2, %3;" : "=r"(d) : "r"(a), "r"(b), "r"(d))

#define ATC(accr, qc, ec, vc)            \
    { u32 s_, t_;                        \
      HADD2A(s_, (qc), (ec));            \
      TANH2A(t_, s_);                    \
      HFMA2A((accr), (vc), t_); }

#define AT4H(accr, q4, e4, v4)           \
    ATC(accr, (q4).x, (e4).x, (v4).x);   \
    ATC(accr, (q4).y, (e4).y, (v4).y);   \
    ATC(accr, (q4).z, (e4).z, (v4).z);   \
    ATC(accr, (q4).w, (e4).w, (v4).w)

__global__ __launch_bounds__(256) void attn_kernel(
    const float* __restrict__ v, float* __restrict__ out) {
    extern __shared__ u32 smu[];
    u32* Qs = smu;               // [64][ASU] half2
    u32* Es = Qs + 64 * ASU;     // [64][ASU] half2
    u32* vs = Es + 64 * ASU;     // [128] half2

    const int tid = threadIdx.x;
    const int b = blockIdx.z, t0 = blockIdx.y << 6, n0 = blockIdx.x << 6;

    if (tid < 128) {
        float2 vv = ((const float2*)v)[tid];
        vs[tid] = packh2(vv.x, vv.y);
    }
    for (int i = tid; i < 2048; i += 256) {
        int row = i >> 5, c4 = i & 31;
        uint4 q = __ldg((const uint4*)(g_Qh + ((size_t)(t0 + row) * B_ + b) * (H_ / 2)) + c4);
        *(uint4*)&Qs[row * ASU + c4 * 4] = q;
        uint4 e = __ldg((const uint4*)(g_Eh + ((size_t)b * N_ + n0 + row) * (H_ / 2)) + c4);
        *(uint4*)&Es[row * ASU + c4 * 4] = e;
    }
    __syncthreads();

    const int tx = tid & 15, ty = tid >> 4;
    float acc[4][4];
#pragma unroll
    for (int i = 0; i < 4; i++)
#pragma unroll
        for (int jj = 0; jj < 4; jj++) acc[i][jj] = 0.f;

    const u32* qp = &Qs[ty * ASU];
    const u32* ep = &Es[tx * ASU];

#pragma unroll 1
    for (int c = 0; c < 16; c++) {      // 16 chunks x 16 h-values
        u32 hacc[4][4];
#pragma unroll
        for (int i = 0; i < 4; i++)
#pragma unroll
            for (int jj = 0; jj < 4; jj++) hacc[i][jj] = 0u;

#pragma unroll
        for (int s = 0; s < 2; s++) {
            const int o = (c * 2 + s) * 4;
            uint4 vv = *(const uint4*)&vs[o];
            uint4 q0 = *(const uint4*)(qp + o);
            uint4 q1 = *(const uint4*)(qp + 16 * ASU + o);
            uint4 q2 = *(const uint4*)(qp + 32 * ASU + o);
            uint4 q3 = *(const uint4*)(qp + 48 * ASU + o);
            uint4 e0 = *(const uint4*)(ep + o);
            uint4 e1 = *(const uint4*)(ep + 16 * ASU + o);
            uint4 e2 = *(const uint4*)(ep + 32 * ASU + o);
            uint4 e3 = *(const uint4*)(ep + 48 * ASU + o);
            AT4H(hacc[0][0], q0, e0, vv); AT4H(hacc[0][1], q0, e1, vv);
            AT4H(hacc[0][2], q0, e2, vv); AT4H(hacc[0][3], q0, e3, vv);
            AT4H(hacc[1][0], q1, e0, vv); AT4H(hacc[1][1], q1, e1, vv);
            AT4H(hacc[1][2], q1, e2, vv); AT4H(hacc[1][3], q1, e3, vv);
            AT4H(hacc[2][0], q2, e0, vv); AT4H(hacc[2][1], q2, e1, vv);
            AT4H(hacc[2][2], q2, e2, vv); AT4H(hacc[2][3], q2, e3, vv);
            AT4H(hacc[3][0], q3, e0, vv); AT4H(hacc[3][1], q3, e1, vv);
            AT4H(hacc[3][2], q3, e2, vv); AT4H(hacc[3][3], q3, e3, vv);
        }
#pragma unroll
        for (int i = 0; i < 4; i++)
#pragma unroll
            for (int jj = 0; jj < 4; jj++) {
                u32 hb = hacc[i][jj];
                acc[i][jj] += h2f_fast(hb) + h2f_fast(hb >> 16);
            }
    }

#pragma unroll
    for (int i = 0; i < 4; i++) {
        float* op = out + ((size_t)b * T_ + t0 + ty + 16 * i) * N_ + n0 + tx;
#pragma unroll
        for (int jj = 0; jj < 4; jj++) op[16 * jj] = acc[i][jj];
    }
}

// ---------------------------------------------------------------------------
extern "C" void kernel_launch(void* const* d_in, const int* in_sizes, int n_in,
                              void* d_out, int out_size) {
    const float* enc   = (const float*)d_in[0];
    const float* W_ih  = (const float*)d_in[1];
    const float* W_hh  = (const float*)d_in[2];
    const float* b_ih  = (const float*)d_in[3];
    const float* b_hh  = (const float*)d_in[4];
    const float* W_ref = (const float*)d_in[5];
    const float* W_q   = (const float*)d_in[6];
    const float* v     = (const float*)d_in[7];
    float* out = (float*)d_out;

    cudaFuncSetAttribute(scan_kernel, cudaFuncAttributeMaxDynamicSharedMemorySize, SCAN_SMEM);
    cudaFuncSetAttribute(attn_kernel, cudaFuncAttributeMaxDynamicSharedMemorySize, ATTN_SMEM);

    void *pEh, *pQh, *pH;
    cudaGetSymbolAddress(&pEh, g_Eh);
    cudaGetSymbolAddress(&pQh, g_Qh);
    cudaGetSymbolAddress(&pH, g_Hall);

    zero_bar<<<1, 32>>>();
    gemm_kernel<<<dim3(1024, 2), 256>>>(enc, W_ref, (u32*)pEh);
    scan_kernel<<<128, 256, SCAN_SMEM>>>(W_ih, W_hh, b_ih, b_hh);
    gemm_kernel<<<dim3(1024, 2), 256>>>((const float*)pH, W_q, (u32*)pQh);
    attn_kernel<<<dim3(8, 8, 256), 256, ATTN_SMEM>>>(v, out);
}

// round 5
// speedup vs baseline: 1.1933x; 1.0248x over previous
#include <cuda_runtime.h>
#include <cuda_fp16.h>
#include <math.h>

#define B_ 256
#define T_ 512
#define N_ 512
#define H_ 256

typedef unsigned long long u64;
typedef unsigned u32;

// ---------------- scratch (device globals; allocation-free) ----------------
__device__ u32   g_Eh[(size_t)B_ * N_ * (H_ / 2)];   // enc_proj half2 [b][n][h2]
__device__ u32   g_Qh[(size_t)T_ * B_ * (H_ / 2)];   // q       half2 [t][b][h2]
__device__ float g_Hall[(size_t)T_ * B_ * H_];       // hiddens f32   [t][b][h]
__device__ float g_hid[2][B_ * H_];                  // double-buffered hid
__device__ unsigned g_barcnt[16 * 32];               // 128B-padded barriers

// ---------------- fast-math helpers ----------------
__device__ __forceinline__ float tanha(float x) {
    float y; asm("tanh.approx.f32 %0, %1;" : "=f"(y) : "f"(x)); return y;
}
__device__ __forceinline__ float sigma_(float x) {
    return fmaf(0.5f, tanha(0.5f * x), 0.5f);
}
__device__ __forceinline__ u64 ffma2(u64 a, u64 b, u64 c) {
    u64 r; asm("fma.rn.f32x2 %0, %1, %2, %3;" : "=l"(r) : "l"(a), "l"(b), "l"(c));
    return r;
}
__device__ __forceinline__ u64 fdup2(float x) {
    u64 r; asm("mov.b64 %0, {%1, %1};" : "=l"(r) : "f"(x)); return r;
}
__device__ __forceinline__ float fsum2(u64 a) {
    float lo, hi; asm("mov.b64 {%0, %1}, %2;" : "=f"(lo), "=f"(hi) : "l"(a));
    return lo + hi;
}
__device__ __forceinline__ float2 funpk(u64 a) {
    float2 f; asm("mov.b64 {%0, %1}, %2;" : "=f"(f.x), "=f"(f.y) : "l"(a));
    return f;
}
__device__ __forceinline__ u32 packh2(float a, float b) {
    __half2 h = __floats2half2_rn(a, b);
    return *reinterpret_cast<u32*>(&h);
}
// half(low 16 bits) -> float, pure ALU (exact for normals)
__device__ __forceinline__ float h2f_fast(u32 hb) {
    u32 r = ((hb & 0x8000u) << 16) + ((hb & 0x7FFFu) << 13) + 0x38000000u;
    return __uint_as_float(r);
}

// ---------------------------------------------------------------------------
// GEMM: OutH[m][k](half2-packed) = sum_h X[m][h] * W[k][h]
// Also zeroes the scan barrier counters (block (0,0)) — ordered by kernel
// boundaries: gemmE zeroes before scan runs; gemmQ re-zeroes after scan done.
// ---------------------------------------------------------------------------
__global__ __launch_bounds__(256) void gemm_kernel(
    const float* __restrict__ X, const float* __restrict__ W,
    u32* __restrict__ OutH) {
    __shared__ __align__(16) float Xs[16][132];
    __shared__ __align__(16) float Ws[16][132];
    const int tid = threadIdx.x;
    if (blockIdx.x == 0 && blockIdx.y == 0 && tid < 16) g_barcnt[tid * 32] = 0u;

    const size_t m0 = (size_t)blockIdx.x * 128;
    const int k0 = blockIdx.y * 128;
    const int f = tid & 3, r = tid >> 2;
    const int tm = tid >> 4, tk = tid & 15;

    const float* Xp = X + (m0 + r) * H_ + f * 4;
    const float* Wp = W + (size_t)(k0 + r) * H_ + f * 4;

    u64 acc[8][4];
#pragma unroll
    for (int i = 0; i < 8; i++)
#pragma unroll
        for (int j = 0; j < 4; j++) acc[i][j] = 0ULL;

    for (int h0 = 0; h0 < H_; h0 += 16) {
        float4 x0 = *(const float4*)(Xp + h0);
        float4 x1 = *(const float4*)(Xp + h0 + (size_t)64 * H_);
        float4 w0 = *(const float4*)(Wp + h0);
        float4 w1 = *(const float4*)(Wp + h0 + (size_t)64 * H_);
        __syncthreads();
        Xs[f * 4 + 0][r] = x0.x; Xs[f * 4 + 1][r] = x0.y;
        Xs[f * 4 + 2][r] = x0.z; Xs[f * 4 + 3][r] = x0.w;
        Xs[f * 4 + 0][r + 64] = x1.x; Xs[f * 4 + 1][r + 64] = x1.y;
        Xs[f * 4 + 2][r + 64] = x1.z; Xs[f * 4 + 3][r + 64] = x1.w;
        Ws[f * 4 + 0][r] = w0.x; Ws[f * 4 + 1][r] = w0.y;
        Ws[f * 4 + 2][r] = w0.z; Ws[f * 4 + 3][r] = w0.w;
        Ws[f * 4 + 0][r + 64] = w1.x; Ws[f * 4 + 1][r + 64] = w1.y;
        Ws[f * 4 + 2][r + 64] = w1.z; Ws[f * 4 + 3][r + 64] = w1.w;
        __syncthreads();
#pragma unroll
        for (int hh = 0; hh < 16; hh++) {
            float xr[8];
            *(float4*)&xr[0] = *(const float4*)&Xs[hh][tm * 8];
            *(float4*)&xr[4] = *(const float4*)&Xs[hh][tm * 8 + 4];
            ulonglong2 wa = *(const ulonglong2*)&Ws[hh][tk * 8];
            ulonglong2 wb = *(const ulonglong2*)&Ws[hh][tk * 8 + 4];
#pragma unroll
            for (int i = 0; i < 8; i++) {
                u64 xd = fdup2(xr[i]);
                acc[i][0] = ffma2(xd, wa.x, acc[i][0]);
                acc[i][1] = ffma2(xd, wa.y, acc[i][1]);
                acc[i][2] = ffma2(xd, wb.x, acc[i][2]);
                acc[i][3] = ffma2(xd, wb.y, acc[i][3]);
            }
        }
    }
#pragma unroll
    for (int i = 0; i < 8; i++) {
        float2 p0 = funpk(acc[i][0]), p1 = funpk(acc[i][1]);
        float2 p2 = funpk(acc[i][2]), p3 = funpk(acc[i][3]);
        uint4 o;
        o.x = packh2(p0.x, p0.y); o.y = packh2(p1.x, p1.y);
        o.z = packh2(p2.x, p2.y); o.w = packh2(p3.x, p3.y);
        u32* op = OutH + (m0 + tm * 8 + i) * (H_ / 2) + (k0 >> 1) + tk * 4;
        *(uint4*)op = o;
    }
}

// ---------------------------------------------------------------------------
// LSTM scan: 16 groups x 8 CTAs; weights smem-resident.
// Warp w: rh=w&1 -> batch rows [8rh,8rh+8), hq=w>>1 -> h-quarter [64hq,64hq+64).
// Lane owns gate-col (all 4 gate types). acc[4 gates][8 rows], 4-way h-reduce.
// Weight smem traffic halved vs R=4 (each weight read by 2 threads/step).
// ---------------------------------------------------------------------------
#define WSS 260
#define REDP 17
#define SCAN_SMEM ((128 * WSS + 16 * 256 + 3 * 128 * REDP + 128) * 4)

#define PDOT4(A, wv, hv)                 \
    A = ffma2((wv).x, (hv).x, A);        \
    A = ffma2((wv).y, (hv).y, A)

__global__ __launch_bounds__(256) void scan_kernel(
    const float* __restrict__ W_ih, const float* __restrict__ W_hh,
    const float* __restrict__ b_ih, const float* __restrict__ b_hh) {
    extern __shared__ float sm[];
    float* Ws = sm;                       // [128][WSS] gate-rows x h
    float* hid_s = Ws + 128 * WSS;        // [16][256]
    float* red = hid_s + 16 * 256;        // [3][128][REDP] partial sums
    float* bcs = red + 3 * 128 * REDP;    // [128]

    const int tid = threadIdx.x;
    const int grp = blockIdx.x >> 3, j = blockIdx.x & 7;
    const int r0 = grp * 16, hbase = j * 32;

    for (int idx = tid; idx < 128 * 256; idx += 256) {
        int q = idx >> 8, h = idx & 255;
        int row = (q >> 5) * 256 + hbase + (q & 31);   // gate-type*256 + hcol
        size_t w = (size_t)row * H_ + h;
        Ws[q * WSS + h] = W_ih[w] + W_hh[w];
    }
    if (tid < 128) {
        int row = (tid >> 5) * 256 + hbase + (tid & 31);
        bcs[tid] = b_ih[row] + b_hh[row];
    }
    for (int idx = tid; idx < 16 * 256; idx += 256) hid_s[idx] = 0.f;
    __syncthreads();

    const int w = tid >> 5, lane = tid & 31;
    const int rh = w & 1, hq = w >> 1, hb = hq * 64;
    float cell[8] = {0.f, 0.f, 0.f, 0.f, 0.f, 0.f, 0.f, 0.f};

    const float* wp0 = &Ws[(0 * 32 + lane) * WSS + hb];
    const float* wp1 = &Ws[(1 * 32 + lane) * WSS + hb];
    const float* wp2 = &Ws[(2 * 32 + lane) * WSS + hb];
    const float* wp3 = &Ws[(3 * 32 + lane) * WSS + hb];
    const float* hp = &hid_s[(rh * 8) * 256 + hb];

    volatile unsigned* barp = &g_barcnt[grp * 32];

    for (int t = 0; t < T_; t++) {
        u64 acc[4][8];
#pragma unroll
        for (int g = 0; g < 4; g++)
#pragma unroll
            for (int r = 0; r < 8; r++) acc[g][r] = 0ULL;

#pragma unroll 4
        for (int c = 0; c < 64; c += 4) {
            ulonglong2 w0 = *(const ulonglong2*)(wp0 + c);
            ulonglong2 w1 = *(const ulonglong2*)(wp1 + c);
            ulonglong2 w2 = *(const ulonglong2*)(wp2 + c);
            ulonglong2 w3 = *(const ulonglong2*)(wp3 + c);
#pragma unroll
            for (int r = 0; r < 8; r++) {
                ulonglong2 hv = *(const ulonglong2*)(hp + r * 256 + c);
                PDOT4(acc[0][r], w0, hv);
                PDOT4(acc[1][r], w1, hv);
                PDOT4(acc[2][r], w2, hv);
                PDOT4(acc[3][r], w3, hv);
            }
        }

        if (hq) {
            float* rp = &red[(size_t)(hq - 1) * 128 * REDP];
#pragma unroll
            for (int g = 0; g < 4; g++)
#pragma unroll
                for (int r = 0; r < 8; r++)
                    rp[(32 * g + lane) * REDP + 8 * rh + r] = fsum2(acc[g][r]);
        }
        __syncthreads();

        const int buf = (t + 1) & 1;
        if (hq == 0) {
#pragma unroll
            for (int r = 0; r < 8; r++) {
                int bat = 8 * rh + r;
                float ig = fsum2(acc[0][r]) + bcs[lane];
                float fg = fsum2(acc[1][r]) + bcs[32 + lane];
                float gg = fsum2(acc[2][r]) + bcs[64 + lane];
                float og = fsum2(acc[3][r]) + bcs[96 + lane];
#pragma unroll
                for (int q = 0; q < 3; q++) {
                    const float* rp = &red[(size_t)q * 128 * REDP];
                    ig += rp[(0 * 32 + lane) * REDP + bat];
                    fg += rp[(1 * 32 + lane) * REDP + bat];
                    gg += rp[(2 * 32 + lane) * REDP + bat];
                    og += rp[(3 * 32 + lane) * REDP + bat];
                }
                cell[r] = sigma_(fg) * cell[r] + sigma_(ig) * tanha(gg);
                float hd = sigma_(og) * tanha(cell[r]);
                int row = r0 + bat, col = hbase + lane;
                g_hid[buf][(row << 8) + col] = hd;
                g_Hall[((size_t)t * B_ + row) * H_ + col] = hd;
            }
        }

        // ---- group barrier (8 CTAs), 128B-padded counter ----
        __syncthreads();
        if (tid == 0) {
            __threadfence();
            atomicAdd((unsigned*)barp, 1u);
            unsigned tgt = (unsigned)(t + 1) * 8u;
            while (*barp < tgt) {}
            __threadfence();
        }
        __syncthreads();

        // ---- reload full hid slice for this group's 16 batch rows ----
        const float4* src = (const float4*)&g_hid[buf][r0 * H_];
        for (int i2 = tid; i2 < 1024; i2 += 256)
            *(float4*)&hid_s[i2 * 4] = __ldcg(src + i2);
        __syncthreads();
    }
}

// ---------------------------------------------------------------------------
// Attention: out[b][t][n] = sum_h v[h]*tanh(E[b][n][h]+Q[t][b][h])
// All-half pipeline: HADD2 -> tanh.f16x2 -> HFMA2 (chunked) -> ALU widen
// ---------------------------------------------------------------------------
#define ASU 132
#define ATTN_SMEM ((2 * 64 * ASU + 128) * 4)

#define HADD2A(r, a, b) asm("add.rn.f16x2 %0, %1, %2;" : "=r"(r) : "r"(a), "r"(b))
#define TANH2A(r, a)    asm("tanh.approx.f16x2 %0, %1;" : "=r"(r) : "r"(a))
#define HFMA2A(d, a, b) asm("fma.rn.f16x2 %0, %1, %2, %3;" : "=r"(d) : "r"(a), "r"(b), "r"(d))

#define ATC(accr, qc, ec, vc)            \
    { u32 s_, t_;                        \
      HADD2A(s_, (qc), (ec));            \
      TANH2A(t_, s_);                    \
      HFMA2A((accr), (vc), t_); }

#define AT4H(accr, q4, e4, v4)           \
    ATC(accr, (q4).x, (e4).x, (v4).x);   \
    ATC(accr, (q4).y, (e4).y, (v4).y);   \
    ATC(accr, (q4).z, (e4).z, (v4).z);   \
    ATC(accr, (q4).w, (e4).w, (v4).w)

__global__ __launch_bounds__(256) void attn_kernel(
    const float* __restrict__ v, float* __restrict__ out) {
    extern __shared__ u32 smu[];
    u32* Qs = smu;               // [64][ASU] half2
    u32* Es = Qs + 64 * ASU;     // [64][ASU] half2
    u32* vs = Es + 64 * ASU;     // [128] half2

    const int tid = threadIdx.x;
    const int b = blockIdx.z, t0 = blockIdx.y << 6, n0 = blockIdx.x << 6;

    if (tid < 128) {
        float2 vv = ((const float2*)v)[tid];
        vs[tid] = packh2(vv.x, vv.y);
    }
    for (int i = tid; i < 2048; i += 256) {
        int row = i >> 5, c4 = i & 31;
        uint4 q = __ldg((const uint4*)(g_Qh + ((size_t)(t0 + row) * B_ + b) * (H_ / 2)) + c4);
        *(uint4*)&Qs[row * ASU + c4 * 4] = q;
        uint4 e = __ldg((const uint4*)(g_Eh + ((size_t)b * N_ + n0 + row) * (H_ / 2)) + c4);
        *(uint4*)&Es[row * ASU + c4 * 4] = e;
    }
    __syncthreads();

    const int tx = tid & 15, ty = tid >> 4;
    float acc[4][4];
#pragma unroll
    for (int i = 0; i < 4; i++)
#pragma unroll
        for (int jj = 0; jj < 4; jj++) acc[i][jj] = 0.f;

    const u32* qp = &Qs[ty * ASU];
    const u32* ep = &Es[tx * ASU];

#pragma unroll 1
    for (int c = 0; c < 16; c++) {
        u32 hacc[4][4];
#pragma unroll
        for (int i = 0; i < 4; i++)
#pragma unroll
            for (int jj = 0; jj < 4; jj++) hacc[i][jj] = 0u;

#pragma unroll
        for (int s = 0; s < 2; s++) {
            const int o = (c * 2 + s) * 4;
            uint4 vv = *(const uint4*)&vs[o];
            uint4 q0 = *(const uint4*)(qp + o);
            uint4 q1 = *(const uint4*)(qp + 16 * ASU + o);
            uint4 q2 = *(const uint4*)(qp + 32 * ASU + o);
            uint4 q3 = *(const uint4*)(qp + 48 * ASU + o);
            uint4 e0 = *(const uint4*)(ep + o);
            uint4 e1 = *(const uint4*)(ep + 16 * ASU + o);
            uint4 e2 = *(const uint4*)(ep + 32 * ASU + o);
            uint4 e3 = *(const uint4*)(ep + 48 * ASU + o);
            AT4H(hacc[0][0], q0, e0, vv); AT4H(hacc[0][1], q0, e1, vv);
            AT4H(hacc[0][2], q0, e2, vv); AT4H(hacc[0][3], q0, e3, vv);
            AT4H(hacc[1][0], q1, e0, vv); AT4H(hacc[1][1], q1, e1, vv);
            AT4H(hacc[1][2], q1, e2, vv); AT4H(hacc[1][3], q1, e3, vv);
            AT4H(hacc[2][0], q2, e0, vv); AT4H(hacc[2][1], q2, e1, vv);
            AT4H(hacc[2][2], q2, e2, vv); AT4H(hacc[2][3], q2, e3, vv);
            AT4H(hacc[3][0], q3, e0, vv); AT4H(hacc[3][1], q3, e1, vv);
            AT4H(hacc[3][2], q3, e2, vv); AT4H(hacc[3][3], q3, e3, vv);
        }
#pragma unroll
        for (int i = 0; i < 4; i++)
#pragma unroll
            for (int jj = 0; jj < 4; jj++) {
                u32 hb = hacc[i][jj];
                acc[i][jj] += h2f_fast(hb) + h2f_fast(hb >> 16);
            }
    }

#pragma unroll
    for (int i = 0; i < 4; i++) {
        float* op = out + ((size_t)b * T_ + t0 + ty + 16 * i) * N_ + n0 + tx;
#pragma unroll
        for (int jj = 0; jj < 4; jj++) op[16 * jj] = acc[i][jj];
    }
}

// ---------------------------------------------------------------------------
extern "C" void kernel_launch(void* const* d_in, const int* in_sizes, int n_in,
                              void* d_out, int out_size) {
    const float* enc   = (const float*)d_in[0];
    const float* W_ih  = (const float*)d_in[1];
    const float* W_hh  = (const float*)d_in[2];
    const float* b_ih  = (const float*)d_in[3];
    const float* b_hh  = (const float*)d_in[4];
    const float* W_ref = (const float*)d_in[5];
    const float* W_q   = (const float*)d_in[6];
    const float* v     = (const float*)d_in[7];
    float* out = (float*)d_out;

    cudaFuncSetAttribute(scan_kernel, cudaFuncAttributeMaxDynamicSharedMemorySize, SCAN_SMEM);
    cudaFuncSetAttribute(attn_kernel, cudaFuncAttributeMaxDynamicSharedMemorySize, ATTN_SMEM);

    void *pEh, *pQh, *pH;
    cudaGetSymbolAddress(&pEh, g_Eh);
    cudaGetSymbolAddress(&pQh, g_Qh);
    cudaGetSymbolAddress(&pH, g_Hall);

    gemm_kernel<<<dim3(1024, 2), 256>>>(enc, W_ref, (u32*)pEh);
    scan_kernel<<<128, 256, SCAN_SMEM>>>(W_ih, W_hh, b_ih, b_hh);
    gemm_kernel<<<dim3(1024, 2), 256>>>((const float*)pH, W_q, (u32*)pQh);
    attn_kernel<<<dim3(8, 8, 256), 256, ATTN_SMEM>>>(v, out);
}

// round 6
// speedup vs baseline: 1.2045x; 1.0093x over previous
#include <cuda_runtime.h>
#include <cuda_fp16.h>
#include <math.h>

#define B_ 256
#define T_ 512
#define N_ 512
#define H_ 256
#define CHUNK 64

typedef unsigned long long u64;
typedef unsigned u32;

// ---------------- scratch (device globals; allocation-free) ----------------
__device__ u32   g_Eh[(size_t)B_ * N_ * (H_ / 2)];   // enc_proj half2 [b][n][h2]
__device__ u32   g_Qh[(size_t)T_ * B_ * (H_ / 2)];   // q       half2 [t][b][h2]
__device__ float g_Hall[(size_t)T_ * B_ * H_];       // hiddens f32   [t][b][h]
__device__ float g_hid[2][B_ * H_];                  // double-buffered hid
__device__ float g_cell[B_ * H_];                    // cell state (chunked scan)
__device__ unsigned g_barcnt[16 * 32];               // 128B-padded barriers

// ---------------- fast-math helpers ----------------
__device__ __forceinline__ float tanha(float x) {
    float y; asm("tanh.approx.f32 %0, %1;" : "=f"(y) : "f"(x)); return y;
}
__device__ __forceinline__ float sigma_(float x) {
    return fmaf(0.5f, tanha(0.5f * x), 0.5f);
}
__device__ __forceinline__ u64 ffma2(u64 a, u64 b, u64 c) {
    u64 r; asm("fma.rn.f32x2 %0, %1, %2, %3;" : "=l"(r) : "l"(a), "l"(b), "l"(c));
    return r;
}
__device__ __forceinline__ u64 fdup2(float x) {
    u64 r; asm("mov.b64 %0, {%1, %1};" : "=l"(r) : "f"(x)); return r;
}
__device__ __forceinline__ float fsum2(u64 a) {
    float lo, hi; asm("mov.b64 {%0, %1}, %2;" : "=f"(lo), "=f"(hi) : "l"(a));
    return lo + hi;
}
__device__ __forceinline__ float2 funpk(u64 a) {
    float2 f; asm("mov.b64 {%0, %1}, %2;" : "=f"(f.x), "=f"(f.y) : "l"(a));
    return f;
}
__device__ __forceinline__ u32 packh2(float a, float b) {
    __half2 h = __floats2half2_rn(a, b);
    return *reinterpret_cast<u32*>(&h);
}
// half(low 16 bits) -> float, pure ALU (exact for normals)
__device__ __forceinline__ float h2f_fast(u32 hb) {
    u32 r = ((hb & 0x8000u) << 16) + ((hb & 0x7FFFu) << 13) + 0x38000000u;
    return __uint_as_float(r);
}
// XOR block swizzle for gemm W-tile smem: block b=k>>3 -> b^(b>>2)
__device__ __forceinline__ int wperm(int k) {
    int b = k >> 3;
    return (((b ^ (b >> 2)) & 15) << 3) | (k & 7);
}

// ---------------------------------------------------------------------------
// GEMM: OutH[m][k](half2-packed) = sum_h X[m][h] * W[k][h]
// Block (0,0) zeroes scan barrier counters (ordered by kernel boundaries).
// ---------------------------------------------------------------------------
__global__ __launch_bounds__(256) void gemm_kernel(
    const float* __restrict__ X, const float* __restrict__ W,
    u32* __restrict__ OutH) {
    __shared__ __align__(16) float Xs[16][132];
    __shared__ __align__(16) float Ws[16][132];
    const int tid = threadIdx.x;
    if (blockIdx.x == 0 && blockIdx.y == 0 && tid < 16) g_barcnt[tid * 32] = 0u;

    const size_t m0 = (size_t)blockIdx.x * 128;
    const int k0 = blockIdx.y * 128;
    const int f = tid & 3, r = tid >> 2;
    const int tm = tid >> 4, tk = tid & 15;
    const int wko = wperm(tk * 8);

    const float* Xp = X + (m0 + r) * H_ + f * 4;
    const float* Wp = W + (size_t)(k0 + r) * H_ + f * 4;
    const int rp0 = wperm(r), rp1 = wperm(r + 64);

    u64 acc[8][4];
#pragma unroll
    for (int i = 0; i < 8; i++)
#pragma unroll
        for (int j = 0; j < 4; j++) acc[i][j] = 0ULL;

    for (int h0 = 0; h0 < H_; h0 += 16) {
        float4 x0 = *(const float4*)(Xp + h0);
        float4 x1 = *(const float4*)(Xp + h0 + (size_t)64 * H_);
        float4 w0 = *(const float4*)(Wp + h0);
        float4 w1 = *(const float4*)(Wp + h0 + (size_t)64 * H_);
        __syncthreads();
        Xs[f * 4 + 0][r] = x0.x; Xs[f * 4 + 1][r] = x0.y;
        Xs[f * 4 + 2][r] = x0.z; Xs[f * 4 + 3][r] = x0.w;
        Xs[f * 4 + 0][r + 64] = x1.x; Xs[f * 4 + 1][r + 64] = x1.y;
        Xs[f * 4 + 2][r + 64] = x1.z; Xs[f * 4 + 3][r + 64] = x1.w;
        Ws[f * 4 + 0][rp0] = w0.x; Ws[f * 4 + 1][rp0] = w0.y;
        Ws[f * 4 + 2][rp0] = w0.z; Ws[f * 4 + 3][rp0] = w0.w;
        Ws[f * 4 + 0][rp1] = w1.x; Ws[f * 4 + 1][rp1] = w1.y;
        Ws[f * 4 + 2][rp1] = w1.z; Ws[f * 4 + 3][rp1] = w1.w;
        __syncthreads();
#pragma unroll
        for (int hh = 0; hh < 16; hh++) {
            float xr[8];
            *(float4*)&xr[0] = *(const float4*)&Xs[hh][tm * 8];
            *(float4*)&xr[4] = *(const float4*)&Xs[hh][tm * 8 + 4];
            ulonglong2 wa = *(const ulonglong2*)&Ws[hh][wko];
            ulonglong2 wb = *(const ulonglong2*)&Ws[hh][wko + 4];
#pragma unroll
            for (int i = 0; i < 8; i++) {
                u64 xd = fdup2(xr[i]);
                acc[i][0] = ffma2(xd, wa.x, acc[i][0]);
                acc[i][1] = ffma2(xd, wa.y, acc[i][1]);
                acc[i][2] = ffma2(xd, wb.x, acc[i][2]);
                acc[i][3] = ffma2(xd, wb.y, acc[i][3]);
            }
        }
    }
#pragma unroll
    for (int i = 0; i < 8; i++) {
        float2 p0 = funpk(acc[i][0]), p1 = funpk(acc[i][1]);
        float2 p2 = funpk(acc[i][2]), p3 = funpk(acc[i][3]);
        uint4 o;
        o.x = packh2(p0.x, p0.y); o.y = packh2(p1.x, p1.y);
        o.z = packh2(p2.x, p2.y); o.w = packh2(p3.x, p3.y);
        u32* op = OutH + (m0 + tm * 8 + i) * (H_ / 2) + (k0 >> 1) + tk * 4;
        *(uint4*)op = o;
    }
}

// ---------------------------------------------------------------------------
// LSTM scan chunk (CHUNK steps): 16 groups x 8 CTAs, 512 threads/CTA.
// Compute: warp w -> rh=w&1 (8 batch rows), hq=w>>1 (32-h chunk); partials to
// P[hq][bat][128] (stride-1, conflict-free). Reduce: warp=batch row,
// lane=h-col, cell in 1 register. CG-style grid-group barrier (release
// atomic + acquire poll; no threadfence/CCTL).
// ---------------------------------------------------------------------------
#define WSS 260
#define SCAN_SMEM ((128 * WSS + 16 * 256 + 8 * 16 * 128 + 128) * 4)

#define PDOT4(A, wv, hv)                 \
    A = ffma2((wv).x, (hv).x, A);        \
    A = ffma2((wv).y, (hv).y, A)

__global__ __launch_bounds__(512) void scan_kernel(
    const float* __restrict__ W_ih, const float* __restrict__ W_hh,
    const float* __restrict__ b_ih, const float* __restrict__ b_hh,
    int t0) {
    extern __shared__ float sm[];
    float* Ws = sm;                       // [128][WSS] gate-rows x h
    float* hid_s = Ws + 128 * WSS;        // [16][256]
    float* P = hid_s + 16 * 256;          // [8 hq][16 bat][128 gr]
    float* bcs = P + 8 * 16 * 128;        // [128]

    const int tid = threadIdx.x;
    const int grp = blockIdx.x >> 3, j = blockIdx.x & 7;
    const int r0 = grp * 16, hbase = j * 32;
    const int w = tid >> 5, lane = tid & 31;

    for (int idx = tid; idx < 128 * 256; idx += 512) {
        int q = idx >> 8, h = idx & 255;
        int row = (q >> 5) * 256 + hbase + (q & 31);   // gate-type*256 + hcol
        size_t ww = (size_t)row * H_ + h;
        Ws[q * WSS + h] = W_ih[ww] + W_hh[ww];
    }
    if (tid < 128) {
        int row = (tid >> 5) * 256 + hbase + (tid & 31);
        bcs[tid] = b_ih[row] + b_hh[row];
    }
    // hid + cell init/load
    float cell;
    if (t0 == 0) {
        for (int idx = tid; idx < 16 * 256; idx += 512) hid_s[idx] = 0.f;
        cell = 0.f;
    } else {
        const float4* src = (const float4*)&g_hid[t0 & 1][r0 * H_];
        for (int i2 = tid; i2 < 1024; i2 += 512)
            *(float4*)&hid_s[i2 * 4] = __ldcg(src + i2);
        cell = __ldcg(&g_cell[(r0 + w) * H_ + hbase + lane]);
    }
    __syncthreads();

    const int rh = w & 1, hq = w >> 1, hb = hq * 32;
    const float* wp0 = &Ws[(0 * 32 + lane) * WSS + hb];
    const float* wp1 = &Ws[(1 * 32 + lane) * WSS + hb];
    const float* wp2 = &Ws[(2 * 32 + lane) * WSS + hb];
    const float* wp3 = &Ws[(3 * 32 + lane) * WSS + hb];
    const float* hp = &hid_s[(rh * 8) * 256 + hb];
    float* pw = &P[hq * 2048 + (rh * 8) * 128 + lane];
    const float* pr = &P[w * 128 + lane];

    unsigned* barp = &g_barcnt[grp * 32];

    for (int tt = 0; tt < CHUNK; tt++) {
        const int t = t0 + tt;
        u64 acc[4][8];
#pragma unroll
        for (int g = 0; g < 4; g++)
#pragma unroll
            for (int r = 0; r < 8; r++) acc[g][r] = 0ULL;

#pragma unroll 2
        for (int c = 0; c < 32; c += 4) {
            ulonglong2 w0 = *(const ulonglong2*)(wp0 + c);
            ulonglong2 w1 = *(const ulonglong2*)(wp1 + c);
            ulonglong2 w2 = *(const ulonglong2*)(wp2 + c);
            ulonglong2 w3 = *(const ulonglong2*)(wp3 + c);
#pragma unroll
            for (int r = 0; r < 8; r++) {
                ulonglong2 hv = *(const ulonglong2*)(hp + r * 256 + c);
                PDOT4(acc[0][r], w0, hv);
                PDOT4(acc[1][r], w1, hv);
                PDOT4(acc[2][r], w2, hv);
                PDOT4(acc[3][r], w3, hv);
            }
        }
        // write partials (stride-1: 1 wavefront per STS)
#pragma unroll
        for (int g = 0; g < 4; g++)
#pragma unroll
            for (int r = 0; r < 8; r++)
                pw[r * 128 + g * 32] = fsum2(acc[g][r]);
        __syncthreads();

        // reduce + gate math: warp w = batch row, lane = h-col
        float gate[4];
#pragma unroll
        for (int ty = 0; ty < 4; ty++) {
            float s = bcs[ty * 32 + lane];
#pragma unroll
            for (int k = 0; k < 8; k++) s += pr[k * 2048 + ty * 32];
            gate[ty] = s;
        }
        cell = sigma_(gate[1]) * cell + sigma_(gate[0]) * tanha(gate[2]);
        float hd = sigma_(gate[3]) * tanha(cell);
        const int buf = (t + 1) & 1;
        g_hid[buf][(r0 + w) * H_ + hbase + lane] = hd;
        g_Hall[((size_t)t * B_ + r0 + w) * H_ + hbase + lane] = hd;

        // ---- CG-style group barrier (8 CTAs): release arrive, acquire poll
        __syncthreads();
        if (tid == 0) {
            asm volatile("red.release.gpu.global.add.u32 [%0], %1;"
                         :: "l"(barp), "r"(1u) : "memory");
            unsigned tgt = (unsigned)(t + 1) * 8u, cur;
            do {
                asm volatile("ld.acquire.gpu.global.u32 %0, [%1];"
                             : "=r"(cur) : "l"(barp) : "memory");
            } while (cur < tgt);
        }
        __syncthreads();

        // reload the group's 16 hid rows
        const float4* src = (const float4*)&g_hid[buf][r0 * H_];
        for (int i2 = tid; i2 < 1024; i2 += 512)
            *(float4*)&hid_s[i2 * 4] = __ldcg(src + i2);
        __syncthreads();
    }

    g_cell[(r0 + w) * H_ + hbase + lane] = cell;
}

// ---------------------------------------------------------------------------
// Attention: out[b][t][n] = sum_h v[h]*tanh(E[b][n][h]+Q[t][b][h])
// All-half pipeline: HADD2 -> tanh.f16x2 -> HFMA2 (chunked) -> ALU widen
// ---------------------------------------------------------------------------
#define ASU 132
#define ATTN_SMEM ((2 * 64 * ASU + 128) * 4)

#define HADD2A(r, a, b) asm("add.rn.f16x2 %0, %1, %2;" : "=r"(r) : "r"(a), "r"(b))
#define TANH2A(r, a)    asm("tanh.approx.f16x2 %0, %1;" : "=r"(r) : "r"(a))
#define HFMA2A(d, a, b) asm("fma.rn.f16x2 %0, %1, %2, %3;" : "=r"(d) : "r"(a), "r"(b), "r"(d))

#define ATC(accr, qc, ec, vc)            \
    { u32 s_, t_;                        \
      HADD2A(s_, (qc), (ec));            \
      TANH2A(t_, s_);                    \
      HFMA2A((accr), (vc), t_); }

#define AT4H(accr, q4, e4, v4)           \
    ATC(accr, (q4).x, (e4).x, (v4).x);   \
    ATC(accr, (q4).y, (e4).y, (v4).y);   \
    ATC(accr, (q4).z, (e4).z, (v4).z);   \
    ATC(accr, (q4).w, (e4).w, (v4).w)

__global__ __launch_bounds__(256) void attn_kernel(
    const float* __restrict__ v, float* __restrict__ out) {
    extern __shared__ u32 smu[];
    u32* Qs = smu;               // [64][ASU] half2
    u32* Es = Qs + 64 * ASU;     // [64][ASU] half2
    u32* vs = Es + 64 * ASU;     // [128] half2

    const int tid = threadIdx.x;
    const int b = blockIdx.z, t0 = blockIdx.y << 6, n0 = blockIdx.x << 6;

    if (tid < 128) {
        float2 vv = ((const float2*)v)[tid];
        vs[tid] = packh2(vv.x, vv.y);
    }
    for (int i = tid; i < 2048; i += 256) {
        int row = i >> 5, c4 = i & 31;
        uint4 q = __ldg((const uint4*)(g_Qh + ((size_t)(t0 + row) * B_ + b) * (H_ / 2)) + c4);
        *(uint4*)&Qs[row * ASU + c4 * 4] = q;
        uint4 e = __ldg((const uint4*)(g_Eh + ((size_t)b * N_ + n0 + row) * (H_ / 2)) + c4);
        *(uint4*)&Es[row * ASU + c4 * 4] = e;
    }
    __syncthreads();

    const int tx = tid & 15, ty = tid >> 4;
    float acc[4][4];
#pragma unroll
    for (int i = 0; i < 4; i++)
#pragma unroll
        for (int jj = 0; jj < 4; jj++) acc[i][jj] = 0.f;

    const u32* qp = &Qs[ty * ASU];
    const u32* ep = &Es[tx * ASU];

#pragma unroll 1
    for (int c = 0; c < 16; c++) {
        u32 hacc[4][4];
#pragma unroll
        for (int i = 0; i < 4; i++)
#pragma unroll
            for (int jj = 0; jj < 4; jj++) hacc[i][jj] = 0u;

#pragma unroll
        for (int s = 0; s < 2; s++) {
            const int o = (c * 2 + s) * 4;
            uint4 vv = *(const uint4*)&vs[o];
            uint4 q0 = *(const uint4*)(qp + o);
            uint4 q1 = *(const uint4*)(qp + 16 * ASU + o);
            uint4 q2 = *(const uint4*)(qp + 32 * ASU + o);
            uint4 q3 = *(const uint4*)(qp + 48 * ASU + o);
            uint4 e0 = *(const uint4*)(ep + o);
            uint4 e1 = *(const uint4*)(ep + 16 * ASU + o);
            uint4 e2 = *(const uint4*)(ep + 32 * ASU + o);
            uint4 e3 = *(const uint4*)(ep + 48 * ASU + o);
            AT4H(hacc[0][0], q0, e0, vv); AT4H(hacc[0][1], q0, e1, vv);
            AT4H(hacc[0][2], q0, e2, vv); AT4H(hacc[0][3], q0, e3, vv);
            AT4H(hacc[1][0], q1, e0, vv); AT4H(hacc[1][1], q1, e1, vv);
            AT4H(hacc[1][2], q1, e2, vv); AT4H(hacc[1][3], q1, e3, vv);
            AT4H(hacc[2][0], q2, e0, vv); AT4H(hacc[2][1], q2, e1, vv);
            AT4H(hacc[2][2], q2, e2, vv); AT4H(hacc[2][3], q2, e3, vv);
            AT4H(hacc[3][0], q3, e0, vv); AT4H(hacc[3][1], q3, e1, vv);
            AT4H(hacc[3][2], q3, e2, vv); AT4H(hacc[3][3], q3, e3, vv);
        }
#pragma unroll
        for (int i = 0; i < 4; i++)
#pragma unroll
            for (int jj = 0; jj < 4; jj++) {
                u32 hb = hacc[i][jj];
                acc[i][jj] += h2f_fast(hb) + h2f_fast(hb >> 16);
            }
    }

#pragma unroll
    for (int i = 0; i < 4; i++) {
        float* op = out + ((size_t)b * T_ + t0 + ty + 16 * i) * N_ + n0 + tx;
#pragma unroll
        for (int jj = 0; jj < 4; jj++) op[16 * jj] = acc[i][jj];
    }
}

// ---------------------------------------------------------------------------
extern "C" void kernel_launch(void* const* d_in, const int* in_sizes, int n_in,
                              void* d_out, int out_size) {
    const float* enc   = (const float*)d_in[0];
    const float* W_ih  = (const float*)d_in[1];
    const float* W_hh  = (const float*)d_in[2];
    const float* b_ih  = (const float*)d_in[3];
    const float* b_hh  = (const float*)d_in[4];
    const float* W_ref = (const float*)d_in[5];
    const float* W_q   = (const float*)d_in[6];
    const float* v     = (const float*)d_in[7];
    float* out = (float*)d_out;

    cudaFuncSetAttribute(scan_kernel, cudaFuncAttributeMaxDynamicSharedMemorySize, SCAN_SMEM);
    cudaFuncSetAttribute(attn_kernel, cudaFuncAttributeMaxDynamicSharedMemorySize, ATTN_SMEM);

    void *pEh, *pQh, *pH;
    cudaGetSymbolAddress(&pEh, g_Eh);
    cudaGetSymbolAddress(&pQh, g_Qh);
    cudaGetSymbolAddress(&pH, g_Hall);

    gemm_kernel<<<dim3(1024, 2), 256>>>(enc, W_ref, (u32*)pEh);
    for (int t0 = 0; t0 < T_; t0 += CHUNK)
        scan_kernel<<<128, 512, SCAN_SMEM>>>(W_ih, W_hh, b_ih, b_hh, t0);
    gemm_kernel<<<dim3(1024, 2), 256>>>((const float*)pH, W_q, (u32*)pQh);
    attn_kernel<<<dim3(8, 8, 256), 256, ATTN_SMEM>>>(v, out);
}